// round 13
// baseline (speedup 1.0000x reference)
#include <cuda_runtime.h>
#include <cuda_bf16.h>
#include <cstdint>

#define T_LEN 4096
#define E_DIM 256
#define H_DIM 512
#define G4    2048
#define TAGS  50
#define NCTA  128

// ---------------- device scratch (no allocations allowed) ----------------
__device__ float g_Gx[2][(size_t)T_LEN * G4];            // x-proj, TRANSPOSED: [t][u][gate]
__device__ unsigned long long g_hp[2][T_LEN][H_DIM];     // packets {tag:32 | h:32}, t-major
__device__ unsigned g_epoch;                             // bumped once per launch

// ---------------- Kernel 1: Gx[dir][t][u*4+q] = (emb[sent[t]] @ W_ih^T + b)[q*512+u] ----
#define BM 64
#define BN 64
#define BK 16

__global__ __launch_bounds__(256) void xproj_kernel(
    const int* __restrict__ sent, const float* __restrict__ emb,
    const float* __restrict__ Wih_f, const float* __restrict__ bih_f, const float* __restrict__ bhh_f,
    const float* __restrict__ Wih_b, const float* __restrict__ bih_b, const float* __restrict__ bhh_b)
{
    const int dir = blockIdx.z;
    const float* __restrict__ Wih = dir ? Wih_b : Wih_f;
    const float* __restrict__ bih = dir ? bih_b : bih_f;
    const float* __restrict__ bhh = dir ? bhh_b : bhh_f;
    float* __restrict__ C = g_Gx[dir];

    // bump epoch once per launch (stream-ordered before the recurrence kernel)
    if (blockIdx.x == 0 && blockIdx.y == 0 && dir == 0 && threadIdx.x == 0) {
        g_epoch = g_epoch + 1u;
    }

    __shared__ float As[BK][BM + 4];
    __shared__ float Bs[BK][BN + 4];
    __shared__ int   sidx[BM];

    const int tid = threadIdx.x;
    const int tx = tid & 15;
    const int ty = tid >> 4;
    const int t0 = blockIdx.y * BM;
    const int n0 = blockIdx.x * BN;

    if (tid < BM) sidx[tid] = sent[t0 + tid];
    __syncthreads();

    float acc[4][4];
#pragma unroll
    for (int i = 0; i < 4; i++)
#pragma unroll
        for (int j = 0; j < 4; j++) acc[i][j] = 0.f;

    const int li = tid >> 2;
    const int lk = (tid & 3) * 4;

    for (int k0 = 0; k0 < E_DIM; k0 += BK) {
        const float4 av = *(const float4*)&emb[(size_t)sidx[li] * E_DIM + k0 + lk];
        const float4 bv = *(const float4*)&Wih[(size_t)(n0 + li) * E_DIM + k0 + lk];
        __syncthreads();
        As[lk + 0][li] = av.x; As[lk + 1][li] = av.y; As[lk + 2][li] = av.z; As[lk + 3][li] = av.w;
        Bs[lk + 0][li] = bv.x; Bs[lk + 1][li] = bv.y; Bs[lk + 2][li] = bv.z; Bs[lk + 3][li] = bv.w;
        __syncthreads();
#pragma unroll
        for (int kk = 0; kk < BK; kk++) {
            const float4 a = *(const float4*)&As[kk][ty * 4];
            const float4 b = *(const float4*)&Bs[kk][tx * 4];
            acc[0][0] = fmaf(a.x, b.x, acc[0][0]); acc[0][1] = fmaf(a.x, b.y, acc[0][1]);
            acc[0][2] = fmaf(a.x, b.z, acc[0][2]); acc[0][3] = fmaf(a.x, b.w, acc[0][3]);
            acc[1][0] = fmaf(a.y, b.x, acc[1][0]); acc[1][1] = fmaf(a.y, b.y, acc[1][1]);
            acc[1][2] = fmaf(a.y, b.z, acc[1][2]); acc[1][3] = fmaf(a.y, b.w, acc[1][3]);
            acc[2][0] = fmaf(a.z, b.x, acc[2][0]); acc[2][1] = fmaf(a.z, b.y, acc[2][1]);
            acc[2][2] = fmaf(a.z, b.z, acc[2][2]); acc[2][3] = fmaf(a.z, b.w, acc[2][3]);
            acc[3][0] = fmaf(a.w, b.x, acc[3][0]); acc[3][1] = fmaf(a.w, b.y, acc[3][1]);
            acc[3][2] = fmaf(a.w, b.z, acc[3][2]); acc[3][3] = fmaf(a.w, b.w, acc[3][3]);
        }
    }

    const int n_base = n0 + tx * 4;
    const int q = n_base >> 9;              // gate index (same for all 4 columns: 64 | 512)
    float4 bias;
    bias.x = bih[n_base + 0] + bhh[n_base + 0];
    bias.y = bih[n_base + 1] + bhh[n_base + 1];
    bias.z = bih[n_base + 2] + bhh[n_base + 2];
    bias.w = bih[n_base + 3] + bhh[n_base + 3];
    const int u_base = n_base & 511;
#pragma unroll
    for (int i = 0; i < 4; i++) {
        const int t = t0 + ty * 4 + i;
        float* ct = &C[(size_t)t * G4 + (size_t)u_base * 4 + q];
        ct[0]  = acc[i][0] + bias.x;
        ct[4]  = acc[i][1] + bias.y;
        ct[8]  = acc[i][2] + bias.z;
        ct[12] = acc[i][3] + bias.w;
    }
}

// ---------------- dummy kernel: shifts ncu -s5 capture window onto lstm_rec -------------
__global__ void align_dummy_kernel() {}

// ---------------- Kernel 2: persistent recurrence, warp-specialized + packed matvec -----
// sigm(x) = 1/(1+e^-x); tanh(x) = 2*sigm(2x)-1
__device__ __forceinline__ float sigmf(float x) { return 1.f / (1.f + __expf(-x)); }
__device__ __forceinline__ unsigned long long fma_f32x2(
    unsigned long long a, unsigned long long b, unsigned long long c) {
    unsigned long long d;
    asm("fma.rn.f32x2 %0, %1, %2, %3;" : "=l"(d) : "l"(a), "l"(b), "l"(c));
    return d;
}

__global__ __launch_bounds__(512, 1) void lstm_rec_kernel(
    const float* __restrict__ Whhf, const float* __restrict__ Whhb)
{
    const int tid  = threadIdx.x;
    const int lane = tid & 31;
    const int w    = tid >> 5;        // warps 0-7 compute, 8-15 poll
    const int bid  = blockIdx.x;
    const int dir  = bid >> 6;        // 0 = forward, 1 = backward
    const int s    = bid & 63;
    const int u0   = s << 3;          // first of 8 hidden units owned by this CTA

    const float* __restrict__ Whh = dir ? Whhb : Whhf;
    const float* __restrict__ Gx  = g_Gx[dir];

    const unsigned epoch = *((volatile unsigned*)&g_epoch);
    const unsigned tagbase = epoch * 4096u;

    __shared__ float h_s[2][H_DIM];   // double-buffered h staging
    __shared__ float gates_s[32];

    // Compute warps: warp w owns rows idx = w*4 + r, r<4; gate q = idx>>3; unit j = idx&7.
    // Units 0-3 -> warps {0,2,4,6} (named bar 1); units 4-7 -> warps {1,3,5,7} (named bar 2).
    const int idx0 = w * 4;
    // Packed weights: wrP[r][jj] = {W[row, 2*lane+64*jj], W[row, 2*lane+64*jj+1]}
    unsigned long long wrP[4][8];
    if (w < 8) {
#pragma unroll
        for (int r = 0; r < 4; r++) {
            const int idx = idx0 + r;
            const int row = (idx >> 3) * H_DIM + u0 + (idx & 7);
#pragma unroll
            for (int jj = 0; jj < 8; jj++) {
                wrP[r][jj] = __ldg((const unsigned long long*)
                                   &Whh[(size_t)row * H_DIM + 2 * lane + 64 * jj]);
            }
        }
    }
    // transposed-Gx offset for this warp's row r (lane r<4): (u0+(idx&7))*4 + (idx>>3)
    int gxoff = -1;
    if (w < 8 && lane < 4) {
        const int idx = idx0 + lane;
        gxoff = (u0 + (idx & 7)) * 4 + (idx >> 3);
    }

    float c_reg = 0.f;   // cell state: warp 0 lanes 0-3 own units 0-3; warp 1 lanes 0-3 own 4-7

    const int tfirst = dir ? (T_LEN - 1) : 0;
    float gx_cur = (gxoff >= 0) ? __ldg(&Gx[(size_t)tfirst * G4 + gxoff]) : 0.f;

    const int ptid = tid - 256;       // poller index 0..255 (valid for w >= 8)

    for (int step = 0; step < T_LEN; step++) {
        const int t   = dir ? (T_LEN - 1 - step) : step;
        const int buf = step & 1;

        if (w >= 8) {
            // -------- poller warps: acquire h_{t-1} (2 packets via one 16B load) --------
            if (step == 0) {
                *(float2*)&h_s[0][2 * ptid] = make_float2(0.f, 0.f);
            } else {
                const int tp = dir ? (t + 1) : (t - 1);
                const unsigned wtag = tagbase + (unsigned)tp;
                const unsigned long long* p = &g_hp[dir][tp][2 * ptid];
                unsigned long long va, vb;
                do {   // each u64 element individually single-copy atomic (R12-proven)
                    asm volatile("ld.volatile.global.v2.u64 {%0,%1}, [%2];"
                                 : "=l"(va), "=l"(vb) : "l"(p));
                } while (((unsigned)(va >> 32) != wtag) | ((unsigned)(vb >> 32) != wtag));
                float2 hv;
                hv.x = __uint_as_float((unsigned)va);
                hv.y = __uint_as_float((unsigned)vb);
                *(float2*)&h_s[buf][2 * ptid] = hv;
            }
            __syncthreads();   // bar1: h_s[buf] complete
        } else {
            // -------- compute warps --------
            float gx_next = 0.f;
            if (gxoff >= 0 && step + 1 < T_LEN) {
                const int tn = dir ? (t - 1) : (t + 1);
                gx_next = __ldg(&Gx[(size_t)tn * G4 + gxoff]);
            }
            __syncthreads();   // bar1: wait for pollers

            // packed matvec: 8 iterations of f32x2 FMA per row (h pair per 8B LDS)
            unsigned long long acc[4] = {0ull, 0ull, 0ull, 0ull};
#pragma unroll
            for (int jj = 0; jj < 8; jj++) {
                const unsigned long long hv =
                    *(const unsigned long long*)&h_s[buf][2 * lane + 64 * jj];
                acc[0] = fma_f32x2(wrP[0][jj], hv, acc[0]);
                acc[1] = fma_f32x2(wrP[1][jj], hv, acc[1]);
                acc[2] = fma_f32x2(wrP[2][jj], hv, acc[2]);
                acc[3] = fma_f32x2(wrP[3][jj], hv, acc[3]);
            }
            float a[4];
#pragma unroll
            for (int r = 0; r < 4; r++) {
                float lo, hi;
                asm("mov.b64 {%0,%1}, %2;" : "=f"(lo), "=f"(hi) : "l"(acc[r]));
                a[r] = lo + hi;
            }
            // fold Gx bias pre-reduce (lane r holds bias for row idx0+r)
            if (lane == 0) a[0] += gx_cur;
            if (lane == 1) a[1] += gx_cur;
            if (lane == 2) a[2] += gx_cur;
            if (lane == 3) a[3] += gx_cur;
            gx_cur = gx_next;
#pragma unroll
            for (int m = 16; m > 0; m >>= 1) {
                a[0] += __shfl_xor_sync(0xffffffffu, a[0], m);
                a[1] += __shfl_xor_sync(0xffffffffu, a[1], m);
                a[2] += __shfl_xor_sync(0xffffffffu, a[2], m);
                a[3] += __shfl_xor_sync(0xffffffffu, a[3], m);
            }
            if (lane < 4) gates_s[idx0 + lane] = a[lane];

            // group barrier: units 0-3 in warps {0,2,4,6}; units 4-7 in warps {1,3,5,7}
            const int grp = w & 1;
            asm volatile("bar.sync %0, %1;" :: "r"(grp + 1), "r"(128) : "memory");

            // group leaders (warps 0 and 1): gates for 4 units, publish immediately
            if (w < 2) {
                const int q = lane >> 2;           // lanes 0-15: (q, j) = (l>>2, l&3)
                const int j = lane & 3;
                float nl = 0.f;
                if (lane < 16) {
                    const float x  = gates_s[q * 8 + grp * 4 + j];
                    const float xs = (q == 2) ? 2.f * x : x;
                    const float sg = sigmf(xs);
                    nl = (q == 2) ? (2.f * sg - 1.f) : sg;   // tanh for gate g, sigm else
                }
                const float iv = __shfl_sync(0xffffffffu, nl, j);
                const float fv = __shfl_sync(0xffffffffu, nl, 4 + j);
                const float gv = __shfl_sync(0xffffffffu, nl, 8 + j);
                const float ov = __shfl_sync(0xffffffffu, nl, 12 + j);
                if (lane < 4) {
                    const float c = fmaf(fv, c_reg, iv * gv);
                    c_reg = c;
                    const float hval = ov * (2.f * sigmf(2.f * c) - 1.f);  // o * tanh(c)
                    const unsigned long long pkt =
                        ((unsigned long long)(tagbase + (unsigned)t) << 32) |
                        (unsigned long long)__float_as_uint(hval);
                    unsigned long long* dst = &g_hp[dir][t][u0 + grp * 4 + lane];
                    asm volatile("st.relaxed.gpu.global.u64 [%0], %1;"
                                 :: "l"(dst), "l"(pkt) : "memory");
                }
            }
        }
        // gates_s hazard: next write happens after next bar1 + matvec, leader reads
        // complete before its own bar1 arrival -> safe without extra barrier
    }
}

// ---------------- Kernel 3: out[t][tag] = concat(hs_f[t], hs_b[t]) @ W_out^T + b_out ----
__global__ __launch_bounds__(256) void outproj_kernel(
    const float* __restrict__ Wout, const float* __restrict__ bout, float* __restrict__ out)
{
    __shared__ float xs[4][2 * H_DIM];
    const int tid = threadIdx.x;
    const int t0 = blockIdx.x * 4;

    for (int i = tid; i < 4 * 2 * H_DIM; i += 256) {
        const int tt = i >> 10;
        const int k  = i & 1023;
        const int t  = t0 + tt;
        const unsigned long long pkt = (k < H_DIM) ? g_hp[0][t][k] : g_hp[1][t][k - H_DIM];
        xs[tt][k] = __uint_as_float((unsigned)pkt);
    }
    __syncthreads();

    const int tag = tid & 63;
    const int tt  = tid >> 6;
    if (tag < TAGS) {
        float acc = __ldg(&bout[tag]);
        const float4* __restrict__ wrow = (const float4*)&Wout[(size_t)tag * (2 * H_DIM)];
        const float4* __restrict__ xv   = (const float4*)xs[tt];
#pragma unroll 8
        for (int k4 = 0; k4 < (2 * H_DIM) / 4; k4++) {
            const float4 wv = __ldg(&wrow[k4]);
            const float4 x  = xv[k4];
            acc = fmaf(wv.x, x.x, acc);
            acc = fmaf(wv.y, x.y, acc);
            acc = fmaf(wv.z, x.z, acc);
            acc = fmaf(wv.w, x.w, acc);
        }
        out[(size_t)(t0 + tt) * TAGS + tag] = acc;
    }
}

// ---------------- launch ----------------
extern "C" void kernel_launch(void* const* d_in, const int* in_sizes, int n_in,
                              void* d_out, int out_size)
{
    const int*   sent  = (const int*)d_in[0];
    const float* emb   = (const float*)d_in[1];
    const float* Wih_f = (const float*)d_in[2];
    const float* Whh_f = (const float*)d_in[3];
    const float* bih_f = (const float*)d_in[4];
    const float* bhh_f = (const float*)d_in[5];
    const float* Wih_b = (const float*)d_in[6];
    const float* Whh_b = (const float*)d_in[7];
    const float* bih_b = (const float*)d_in[8];
    const float* bhh_b = (const float*)d_in[9];
    const float* Wout  = (const float*)d_in[10];
    const float* bout  = (const float*)d_in[11];
    float* out = (float*)d_out;

    dim3 gx(G4 / BN, T_LEN / BM, 2);
    xproj_kernel<<<gx, 256>>>(sent, emb, Wih_f, bih_f, bhh_f, Wih_b, bih_b, bhh_b);
    align_dummy_kernel<<<1, 32>>>();
    align_dummy_kernel<<<1, 32>>>();
    lstm_rec_kernel<<<NCTA, 512>>>(Whh_f, Whh_b);
    outproj_kernel<<<T_LEN / 4, 256>>>(Wout, bout, out);
}

// round 14
// speedup vs baseline: 1.1165x; 1.1165x over previous
#include <cuda_runtime.h>
#include <cuda_bf16.h>
#include <cstdint>

#define T_LEN 4096
#define E_DIM 256
#define H_DIM 512
#define G4    2048
#define TAGS  50
#define NCTA  128   // each CTA owns 4 fwd units AND 4 bwd units

// ---------------- device scratch (no allocations allowed) ----------------
__device__ float g_Gx[2][(size_t)T_LEN * G4];            // x-proj, TRANSPOSED: [t][u][gate]
__device__ unsigned long long g_hp[2][T_LEN][H_DIM];     // packets {tag:32 | h:32}, t-major
__device__ unsigned g_epoch;                             // bumped once per launch

// ---------------- Kernel 1: Gx[dir][t][u*4+q] = (emb[sent[t]] @ W_ih^T + b)[q*512+u] ----
#define BM 64
#define BN 64
#define BK 16

__global__ __launch_bounds__(256) void xproj_kernel(
    const int* __restrict__ sent, const float* __restrict__ emb,
    const float* __restrict__ Wih_f, const float* __restrict__ bih_f, const float* __restrict__ bhh_f,
    const float* __restrict__ Wih_b, const float* __restrict__ bih_b, const float* __restrict__ bhh_b)
{
    const int dir = blockIdx.z;
    const float* __restrict__ Wih = dir ? Wih_b : Wih_f;
    const float* __restrict__ bih = dir ? bih_b : bih_f;
    const float* __restrict__ bhh = dir ? bhh_b : bhh_f;
    float* __restrict__ C = g_Gx[dir];

    // bump epoch once per launch (stream-ordered before the recurrence kernel)
    if (blockIdx.x == 0 && blockIdx.y == 0 && dir == 0 && threadIdx.x == 0) {
        g_epoch = g_epoch + 1u;
    }

    __shared__ float As[BK][BM + 4];
    __shared__ float Bs[BK][BN + 4];
    __shared__ int   sidx[BM];

    const int tid = threadIdx.x;
    const int tx = tid & 15;
    const int ty = tid >> 4;
    const int t0 = blockIdx.y * BM;
    const int n0 = blockIdx.x * BN;

    if (tid < BM) sidx[tid] = sent[t0 + tid];
    __syncthreads();

    float acc[4][4];
#pragma unroll
    for (int i = 0; i < 4; i++)
#pragma unroll
        for (int j = 0; j < 4; j++) acc[i][j] = 0.f;

    const int li = tid >> 2;
    const int lk = (tid & 3) * 4;

    for (int k0 = 0; k0 < E_DIM; k0 += BK) {
        const float4 av = *(const float4*)&emb[(size_t)sidx[li] * E_DIM + k0 + lk];
        const float4 bv = *(const float4*)&Wih[(size_t)(n0 + li) * E_DIM + k0 + lk];
        __syncthreads();
        As[lk + 0][li] = av.x; As[lk + 1][li] = av.y; As[lk + 2][li] = av.z; As[lk + 3][li] = av.w;
        Bs[lk + 0][li] = bv.x; Bs[lk + 1][li] = bv.y; Bs[lk + 2][li] = bv.z; Bs[lk + 3][li] = bv.w;
        __syncthreads();
#pragma unroll
        for (int kk = 0; kk < BK; kk++) {
            const float4 a = *(const float4*)&As[kk][ty * 4];
            const float4 b = *(const float4*)&Bs[kk][tx * 4];
            acc[0][0] = fmaf(a.x, b.x, acc[0][0]); acc[0][1] = fmaf(a.x, b.y, acc[0][1]);
            acc[0][2] = fmaf(a.x, b.z, acc[0][2]); acc[0][3] = fmaf(a.x, b.w, acc[0][3]);
            acc[1][0] = fmaf(a.y, b.x, acc[1][0]); acc[1][1] = fmaf(a.y, b.y, acc[1][1]);
            acc[1][2] = fmaf(a.y, b.z, acc[1][2]); acc[1][3] = fmaf(a.y, b.w, acc[1][3]);
            acc[2][0] = fmaf(a.z, b.x, acc[2][0]); acc[2][1] = fmaf(a.z, b.y, acc[2][1]);
            acc[2][2] = fmaf(a.z, b.z, acc[2][2]); acc[2][3] = fmaf(a.z, b.w, acc[2][3]);
            acc[3][0] = fmaf(a.w, b.x, acc[3][0]); acc[3][1] = fmaf(a.w, b.y, acc[3][1]);
            acc[3][2] = fmaf(a.w, b.z, acc[3][2]); acc[3][3] = fmaf(a.w, b.w, acc[3][3]);
        }
    }

    const int n_base = n0 + tx * 4;
    const int q = n_base >> 9;              // gate index (same for all 4 columns: 64 | 512)
    float4 bias;
    bias.x = bih[n_base + 0] + bhh[n_base + 0];
    bias.y = bih[n_base + 1] + bhh[n_base + 1];
    bias.z = bih[n_base + 2] + bhh[n_base + 2];
    bias.w = bih[n_base + 3] + bhh[n_base + 3];
    const int u_base = n_base & 511;
#pragma unroll
    for (int i = 0; i < 4; i++) {
        const int t = t0 + ty * 4 + i;
        float* ct = &C[(size_t)t * G4 + (size_t)u_base * 4 + q];
        ct[0]  = acc[i][0] + bias.x;
        ct[4]  = acc[i][1] + bias.y;
        ct[8]  = acc[i][2] + bias.z;
        ct[12] = acc[i][3] + bias.w;
    }
}

// ---------------- dummy kernel: shifts ncu -s5 capture window onto lstm_rec -------------
__global__ void align_dummy_kernel() {}

// ---------------- Kernel 2: persistent recurrence, dual-direction interleaved CTAs ------
// Each CTA runs BOTH chains: phase F (fwd) then phase B (bwd) per round. The L2
// propagation of each phase's publish is hidden behind the other phase's compute.
// sigm(x) = 1/(1+e^-x); tanh(x) = 2*sigm(2x)-1
__device__ __forceinline__ float sigmf(float x) { return 1.f / (1.f + __expf(-x)); }

__global__ __launch_bounds__(512, 1) void lstm_rec_kernel(
    const float* __restrict__ Whhf, const float* __restrict__ Whhb)
{
    const int tid  = threadIdx.x;
    const int lane = tid & 31;
    const int w    = tid >> 5;        // 16 warps; warp w owns row idx=w per phase
    const int s    = blockIdx.x;      // 0..127
    const int u0   = s << 2;          // 4 units per direction owned by this CTA

    const unsigned epoch = *((volatile unsigned*)&g_epoch);
    const unsigned tagbase = epoch * 4096u;

    __shared__ float h_s[2][2][H_DIM];     // [dir][buf][unit]
    __shared__ float gates_s[2][2][16];    // [dir][buf][row]

    // warp w -> gate q = w>>2, unit j = w&3; row = q*512 + u0 + j  (same for both dirs)
    const int q = w >> 2;
    const int j = w & 3;
    const int row = q * H_DIM + u0 + j;
    float wrF[16], wrB[16];
#pragma unroll
    for (int jj = 0; jj < 16; jj++) {
        wrF[jj] = __ldg(&Whhf[(size_t)row * H_DIM + lane + 32 * jj]);
        wrB[jj] = __ldg(&Whhb[(size_t)row * H_DIM + lane + 32 * jj]);
    }
    const int gxoff = (u0 + j) * 4 + q;    // transposed-Gx offset (lane 0 of each warp)

    float cF = 0.f, cB = 0.f;              // cell states: warp 0 lanes 0-3 own 4 units/dir

    float gxF_cur = (lane == 0) ? __ldg(&g_Gx[0][gxoff]) : 0.f;                      // t=0
    float gxB_cur = (lane == 0) ? __ldg(&g_Gx[1][(size_t)(T_LEN - 1) * G4 + gxoff]) : 0.f;

    for (int step = 0; step < T_LEN; step++) {
        const int buf = step & 1;

        // ================= phase F: forward chain, t = step =================
        {
            const int t = step;
            float gx_next = 0.f;
            if (lane == 0 && step + 1 < T_LEN)
                gx_next = __ldg(&g_Gx[0][(size_t)(t + 1) * G4 + gxoff]);

            if (step == 0) {
                h_s[0][0][tid] = 0.f;
            } else {
                const unsigned wtag = tagbase + (unsigned)(t - 1);
                const unsigned long long* p = &g_hp[0][t - 1][tid];
                unsigned long long v;
                do {   // published a full phase-B ago -> normally hits first try
                    asm volatile("ld.relaxed.gpu.global.u64 %0, [%1];" : "=l"(v) : "l"(p));
                } while ((unsigned)(v >> 32) != wtag);
                h_s[0][buf][tid] = __uint_as_float((unsigned)v);
            }
            __syncthreads();   // h_s[0][buf] complete

            float a = 0.f;
#pragma unroll
            for (int jj = 0; jj < 16; jj++)
                a = fmaf(wrF[jj], h_s[0][buf][lane + (jj << 5)], a);
            if (lane == 0) a += gxF_cur;
            gxF_cur = gx_next;
#pragma unroll
            for (int m = 16; m > 0; m >>= 1)
                a += __shfl_xor_sync(0xffffffffu, a, m);
            if (lane == 0) gates_s[0][buf][w] = a;
            __syncthreads();   // gates_s[0][buf] complete

            if (w == 0) {      // warp 0: gates for the 4 fwd units, publish immediately
                const int ql = lane >> 2, jl = lane & 3;
                float nl = 0.f;
                if (lane < 16) {
                    const float x  = gates_s[0][buf][lane];
                    const float xs = (ql == 2) ? 2.f * x : x;
                    const float sg = sigmf(xs);
                    nl = (ql == 2) ? (2.f * sg - 1.f) : sg;
                }
                const float iv = __shfl_sync(0xffffffffu, nl, jl);
                const float fv = __shfl_sync(0xffffffffu, nl, 4 + jl);
                const float gv = __shfl_sync(0xffffffffu, nl, 8 + jl);
                const float ov = __shfl_sync(0xffffffffu, nl, 12 + jl);
                if (lane < 4) {
                    const float c = fmaf(fv, cF, iv * gv);
                    cF = c;
                    const float hval = ov * (2.f * sigmf(2.f * c) - 1.f);
                    const unsigned long long pkt =
                        ((unsigned long long)(tagbase + (unsigned)t) << 32) |
                        (unsigned long long)__float_as_uint(hval);
                    unsigned long long* dst = &g_hp[0][t][u0 + lane];
                    asm volatile("st.relaxed.gpu.global.u64 [%0], %1;"
                                 :: "l"(dst), "l"(pkt) : "memory");
                }
            }
        }

        // ================= phase B: backward chain, tb = T-1-step =================
        {
            const int tb = T_LEN - 1 - step;
            float gx_next = 0.f;
            if (lane == 0 && step + 1 < T_LEN)
                gx_next = __ldg(&g_Gx[1][(size_t)(tb - 1) * G4 + gxoff]);

            if (step == 0) {
                h_s[1][0][tid] = 0.f;
            } else {
                const unsigned wtag = tagbase + (unsigned)(tb + 1);
                const unsigned long long* p = &g_hp[1][tb + 1][tid];
                unsigned long long v;
                do {   // published a full phase-F ago -> normally hits first try
                    asm volatile("ld.relaxed.gpu.global.u64 %0, [%1];" : "=l"(v) : "l"(p));
                } while ((unsigned)(v >> 32) != wtag);
                h_s[1][buf][tid] = __uint_as_float((unsigned)v);
            }
            __syncthreads();   // h_s[1][buf] complete

            float a = 0.f;
#pragma unroll
            for (int jj = 0; jj < 16; jj++)
                a = fmaf(wrB[jj], h_s[1][buf][lane + (jj << 5)], a);
            if (lane == 0) a += gxB_cur;
            gxB_cur = gx_next;
#pragma unroll
            for (int m = 16; m > 0; m >>= 1)
                a += __shfl_xor_sync(0xffffffffu, a, m);
            if (lane == 0) gates_s[1][buf][w] = a;
            __syncthreads();   // gates_s[1][buf] complete

            if (w == 0) {      // warp 0: gates for the 4 bwd units, publish immediately
                const int ql = lane >> 2, jl = lane & 3;
                float nl = 0.f;
                if (lane < 16) {
                    const float x  = gates_s[1][buf][lane];
                    const float xs = (ql == 2) ? 2.f * x : x;
                    const float sg = sigmf(xs);
                    nl = (ql == 2) ? (2.f * sg - 1.f) : sg;
                }
                const float iv = __shfl_sync(0xffffffffu, nl, jl);
                const float fv = __shfl_sync(0xffffffffu, nl, 4 + jl);
                const float gv = __shfl_sync(0xffffffffu, nl, 8 + jl);
                const float ov = __shfl_sync(0xffffffffu, nl, 12 + jl);
                if (lane < 4) {
                    const float c = fmaf(fv, cB, iv * gv);
                    cB = c;
                    const float hval = ov * (2.f * sigmf(2.f * c) - 1.f);
                    const unsigned long long pkt =
                        ((unsigned long long)(tagbase + (unsigned)tb) << 32) |
                        (unsigned long long)__float_as_uint(hval);
                    unsigned long long* dst = &g_hp[1][tb][u0 + lane];
                    asm volatile("st.relaxed.gpu.global.u64 [%0], %1;"
                                 :: "l"(dst), "l"(pkt) : "memory");
                }
            }
        }
        // h_s / gates_s hazards handled by per-direction double buffering (buf parity)
    }
}

// ---------------- Kernel 3: out[t][tag] = concat(hs_f[t], hs_b[t]) @ W_out^T + b_out ----
__global__ __launch_bounds__(256) void outproj_kernel(
    const float* __restrict__ Wout, const float* __restrict__ bout, float* __restrict__ out)
{
    __shared__ float xs[4][2 * H_DIM];
    const int tid = threadIdx.x;
    const int t0 = blockIdx.x * 4;

    for (int i = tid; i < 4 * 2 * H_DIM; i += 256) {
        const int tt = i >> 10;
        const int k  = i & 1023;
        const int t  = t0 + tt;
        const unsigned long long pkt = (k < H_DIM) ? g_hp[0][t][k] : g_hp[1][t][k - H_DIM];
        xs[tt][k] = __uint_as_float((unsigned)pkt);
    }
    __syncthreads();

    const int tag = tid & 63;
    const int tt  = tid >> 6;
    if (tag < TAGS) {
        float acc = __ldg(&bout[tag]);
        const float4* __restrict__ wrow = (const float4*)&Wout[(size_t)tag * (2 * H_DIM)];
        const float4* __restrict__ xv   = (const float4*)xs[tt];
#pragma unroll 8
        for (int k4 = 0; k4 < (2 * H_DIM) / 4; k4++) {
            const float4 wv = __ldg(&wrow[k4]);
            const float4 x  = xv[k4];
            acc = fmaf(wv.x, x.x, acc);
            acc = fmaf(wv.y, x.y, acc);
            acc = fmaf(wv.z, x.z, acc);
            acc = fmaf(wv.w, x.w, acc);
        }
        out[(size_t)(t0 + tt) * TAGS + tag] = acc;
    }
}

// ---------------- launch ----------------
extern "C" void kernel_launch(void* const* d_in, const int* in_sizes, int n_in,
                              void* d_out, int out_size)
{
    const int*   sent  = (const int*)d_in[0];
    const float* emb   = (const float*)d_in[1];
    const float* Wih_f = (const float*)d_in[2];
    const float* Whh_f = (const float*)d_in[3];
    const float* bih_f = (const float*)d_in[4];
    const float* bhh_f = (const float*)d_in[5];
    const float* Wih_b = (const float*)d_in[6];
    const float* Whh_b = (const float*)d_in[7];
    const float* bih_b = (const float*)d_in[8];
    const float* bhh_b = (const float*)d_in[9];
    const float* Wout  = (const float*)d_in[10];
    const float* bout  = (const float*)d_in[11];
    float* out = (float*)d_out;

    dim3 gx(G4 / BN, T_LEN / BM, 2);
    xproj_kernel<<<gx, 256>>>(sent, emb, Wih_f, bih_f, bhh_f, Wih_b, bih_b, bhh_b);
    align_dummy_kernel<<<1, 32>>>();
    align_dummy_kernel<<<1, 32>>>();
    lstm_rec_kernel<<<NCTA, 512>>>(Whh_f, Whh_b);
    outproj_kernel<<<T_LEN / 4, 256>>>(Wout, bout, out);
}